// round 4
// baseline (speedup 1.0000x reference)
#include <cuda_runtime.h>
#include <cstdint>
#include <math.h>

#define LAYERS 3
#define UNITS  1024
#define BATCH  128
#define TSEQ   256
#define NC     (3*UNITS)      // 3072
#define MXW    (BATCH*TSEQ)   // 32768

// persistent-kernel geometry: grid = 64 u-groups x 2 batch-halves = 128 CTAs
#define UGRP   64
#define UB     16             // u-indices per CTA
#define CCOLS  48             // 3 gates x UB
#define MROWS  64             // batch rows per CTA (half of BATCH)
#define KC     32             // k-chunk per cp.async stage
#define NCH    (UNITS/KC)     // 32 chunks
#define NSTG   3              // cp.async stages
#define ASTR   72             // A smem row stride (mod32==8 -> conflict-free frags)
#define HUSTR  49

// ---------------- scratch (static device memory) ----------------
__device__ __align__(128) float g_xw[(size_t)MXW * NC];      // [t][b][3U]
__device__ __align__(128) float g_x [(size_t)MXW * UNITS];   // inter-layer activations (tf32)
__device__ __align__(128) float g_hT[2][UNITS][BATCH];       // tf32 h, transposed
__device__ __align__(128) float g_hF[BATCH * UNITS];         // full-precision h
__device__ unsigned g_bar_cnt = 0;
__device__ volatile unsigned g_bar_gen = 0;

// ---------------- helpers ----------------
__device__ __forceinline__ float tf32r(float v) {
    unsigned r;
    asm("cvt.rna.tf32.f32 %0, %1;" : "=r"(r) : "f"(v));
    return __uint_as_float(r);
}

__device__ __forceinline__ void mma_tf32(float* c, const unsigned* a, const unsigned* b) {
    asm volatile(
        "mma.sync.aligned.m16n8k8.row.col.f32.tf32.tf32.f32 "
        "{%0,%1,%2,%3}, {%4,%5,%6,%7}, {%8,%9}, {%0,%1,%2,%3};"
        : "+f"(c[0]), "+f"(c[1]), "+f"(c[2]), "+f"(c[3])
        : "r"(a[0]), "r"(a[1]), "r"(a[2]), "r"(a[3]), "r"(b[0]), "r"(b[1]));
}

__device__ __forceinline__ void cp16(float* dst, const float* src) {
    unsigned ds = (unsigned)__cvta_generic_to_shared(dst);
    asm volatile("cp.async.cg.shared.global [%0], [%1], 16;" :: "r"(ds), "l"(src));
}
__device__ __forceinline__ void cp_commit() { asm volatile("cp.async.commit_group;"); }
template <int N> __device__ __forceinline__ void cp_wait() {
    asm volatile("cp.async.wait_group %0;" :: "n"(N));
}

// grid-wide barrier (128 CTAs, 1/SM, co-resident)
__device__ __forceinline__ void grid_sync() {
    __threadfence();
    __syncthreads();
    if (threadIdx.x == 0) {
        unsigned gen = g_bar_gen;
        if (atomicAdd(&g_bar_cnt, 1u) == 2 * UGRP - 1) {
            g_bar_cnt = 0;
            __threadfence();
            g_bar_gen = gen + 1;
        } else {
            while (g_bar_gen == gen) { __nanosleep(32); }
        }
        __threadfence();
    }
    __syncthreads();
}

// ---------------- XW GEMM: g_xw[t][b][:] = (x @ tf32(W[l])) + b0[l] ----------------
#define BM 128
#define BN 128
#define BK 32
#define GASTR (BM + 1)
#define GBSTR (BN + 1)

__global__ __launch_bounds__(256) void gemm_xw_kernel(const float* __restrict__ A,
                                                      const float* __restrict__ Bw,
                                                      const float* __restrict__ bias) {
    __shared__ float As[BK * GASTR];   // [k][m]
    __shared__ float Bs[BK * GBSTR];   // [k][n]
    float* C = g_xw;

    int tid = threadIdx.x;
    int lane = tid & 31, wid = tid >> 5;
    int gid = lane >> 2, tig = lane & 3;
    int wm = wid & 3, wn = wid >> 2;
    int mb = wm * 32, nb = wn * 64;
    int bm0 = blockIdx.y * BM, bn0 = blockIdx.x * BN;

    float acc[2][8][4];
#pragma unroll
    for (int i = 0; i < 2; i++)
#pragma unroll
        for (int j = 0; j < 8; j++)
#pragma unroll
            for (int q = 0; q < 4; q++) acc[i][j][q] = 0.f;

    for (int k0 = 0; k0 < UNITS; k0 += BK) {
#pragma unroll
        for (int j = 0; j < 4; j++) {
            int i = tid + j * 256;
            int r = i >> 3, c4 = i & 7;
            const float4 v = *(const float4*)(A + (size_t)(bm0 + r) * UNITS + k0 + c4 * 4);
            As[(c4 * 4 + 0) * GASTR + r] = tf32r(v.x);
            As[(c4 * 4 + 1) * GASTR + r] = tf32r(v.y);
            As[(c4 * 4 + 2) * GASTR + r] = tf32r(v.z);
            As[(c4 * 4 + 3) * GASTR + r] = tf32r(v.w);
        }
#pragma unroll
        for (int j = 0; j < 4; j++) {
            int i = tid + j * 256;
            int r = i >> 5, c4 = i & 31;
            const float4 v = *(const float4*)(Bw + (size_t)(k0 + r) * NC + bn0 + c4 * 4);
            Bs[r * GBSTR + c4 * 4 + 0] = tf32r(v.x);
            Bs[r * GBSTR + c4 * 4 + 1] = tf32r(v.y);
            Bs[r * GBSTR + c4 * 4 + 2] = tf32r(v.z);
            Bs[r * GBSTR + c4 * 4 + 3] = tf32r(v.w);
        }
        __syncthreads();
#pragma unroll
        for (int kk = 0; kk < BK; kk += 8) {
            unsigned a[2][4], bf[8][2];
#pragma unroll
            for (int mt = 0; mt < 2; mt++) {
                int m = mb + mt * 16 + gid;
                a[mt][0] = __float_as_uint(As[(kk + tig) * GASTR + m]);
                a[mt][1] = __float_as_uint(As[(kk + tig) * GASTR + m + 8]);
                a[mt][2] = __float_as_uint(As[(kk + tig + 4) * GASTR + m]);
                a[mt][3] = __float_as_uint(As[(kk + tig + 4) * GASTR + m + 8]);
            }
#pragma unroll
            for (int nt = 0; nt < 8; nt++) {
                int n = nb + nt * 8 + gid;
                bf[nt][0] = __float_as_uint(Bs[(kk + tig) * GBSTR + n]);
                bf[nt][1] = __float_as_uint(Bs[(kk + tig + 4) * GBSTR + n]);
            }
#pragma unroll
            for (int mt = 0; mt < 2; mt++)
#pragma unroll
                for (int nt = 0; nt < 8; nt++) mma_tf32(acc[mt][nt], a[mt], bf[nt]);
        }
        __syncthreads();
    }
#pragma unroll
    for (int mt = 0; mt < 2; mt++) {
#pragma unroll
        for (int nt = 0; nt < 8; nt++) {
            int m0 = bm0 + mb + mt * 16 + gid;    // row = b*TSEQ + t
            int n  = bn0 + nb + nt * 8 + 2 * tig;
            float bv0 = bias[n], bv1 = bias[n + 1];
            int t0 = m0 & (TSEQ - 1), b0r = m0 >> 8;
            int m1 = m0 + 8;
            int t1 = m1 & (TSEQ - 1), b1r = m1 >> 8;
            size_t r0 = ((size_t)t0 * BATCH + b0r) * NC + n;
            size_t r1 = ((size_t)t1 * BATCH + b1r) * NC + n;
            C[r0]     = acc[mt][nt][0] + bv0;
            C[r0 + 1] = acc[mt][nt][1] + bv1;
            C[r1]     = acc[mt][nt][2] + bv0;
            C[r1 + 1] = acc[mt][nt][3] + bv1;
        }
    }
}

// ---------------- persistent GRU layer kernel ----------------
// grid (UGRP, 2): blockIdx.x = u-group, blockIdx.y = batch half.
// 256 threads (8 warps: 4 m-warps x 2 n-warps; warp tile m16 n24).
__global__ __launch_bounds__(256, 1)
void gru_layer_kernel(int layer, const float* __restrict__ h0,
                      const float* __restrict__ U_raw,
                      const float* __restrict__ bias1,
                      float* __restrict__ yout, float* __restrict__ out_states,
                      int is_last) {
    extern __shared__ float sm[];
    float* Us    = sm;                          // [1024][48]
    float* Ab    = sm + UNITS * CCOLS;          // NSTG x [KC][ASTR]
    float* sbias = Ab + NSTG * KC * ASTR;       // [48]
    float* HU    = Ab;                          // reuse after mma loop: [64][49]

    const int tid  = threadIdx.x;
    const int lane = tid & 31, wid = tid >> 5;
    const int gid  = lane >> 2, tig = lane & 3;
    const int wm   = wid & 3, wn = wid >> 2;
    const int mb   = wm * 16, nb = wn * 24;
    const int u0   = blockIdx.x * UB;
    const int bh   = blockIdx.y;                // 0 or 1
    const int b0g  = bh * MROWS;

    // load + round U slice (once per layer): Us[k][gate*16+uu]
    const float* Uc = U_raw + (size_t)layer * UNITS * NC;
    for (int i = tid; i < UNITS * 12; i += 256) {
        int k = i / 12, f4 = i % 12;
        int gate = f4 >> 2, uu = (f4 & 3) * 4;
        float4 v = *(const float4*)(Uc + (size_t)k * NC + gate * UNITS + u0 + uu);
        float* d = Us + k * CCOLS + gate * UB + uu;
        d[0] = tf32r(v.x); d[1] = tf32r(v.y); d[2] = tf32r(v.z); d[3] = tf32r(v.w);
    }
    if (tid < CCOLS) {
        int gate = tid >> 4, uu = tid & 15;
        sbias[tid] = bias1[gate * UNITS + u0 + uu];
    }

    // epilogue cell ownership: b = b0g + (tid>>2), u = u0 + (tid&3)*4 + j
    const int eb  = b0g + (tid >> 2);
    const int eu4 = (tid & 3) * 4;

    // init h: full precision -> g_hF, tf32 transposed -> g_hT[0]
    {
        float4 hv;
        const float* src = h0 + ((size_t)eb * UNITS + u0 + eu4) * LAYERS + layer;
        hv.x = src[0]; hv.y = src[3]; hv.z = src[6]; hv.w = src[9];
        *(float4*)(g_hF + (size_t)eb * UNITS + u0 + eu4) = hv;
        g_hT[0][u0 + eu4 + 0][eb] = tf32r(hv.x);
        g_hT[0][u0 + eu4 + 1][eb] = tf32r(hv.y);
        g_hT[0][u0 + eu4 + 2][eb] = tf32r(hv.z);
        g_hT[0][u0 + eu4 + 3][eb] = tf32r(hv.w);
    }
    grid_sync();

    for (int t = 0; t < TSEQ; t++) {
        const int rb = t & 1;
        const float* hTp = &g_hT[rb][0][b0g];   // rows stride BATCH, 64 cols

        // prefetch epilogue operands (independent of h(t) GEMM)
        const float* xwrow = g_xw + ((size_t)t * BATCH + eb) * NC + u0 + eu4;
        float4 xz4 = *(const float4*)(xwrow);
        float4 xr4 = *(const float4*)(xwrow + UNITS);
        float4 xh4 = *(const float4*)(xwrow + 2 * UNITS);
        float4 hp4 = *(const float4*)(g_hF + (size_t)eb * UNITS + u0 + eu4);

        float acc[3][4];
#pragma unroll
        for (int j = 0; j < 3; j++)
#pragma unroll
            for (int q = 0; q < 4; q++) acc[j][q] = 0.f;

        // prologue: chunks 0,1
#pragma unroll
        for (int p = 0; p < 2; p++) {
            float* db = Ab + p * KC * ASTR;
#pragma unroll
            for (int w = 0; w < 2; w++) {
                int i = tid + w * 256;
                int k = i >> 4, c16 = i & 15;
                cp16(db + k * ASTR + c16 * 4, hTp + (p * KC + k) * BATCH + c16 * 4);
            }
            cp_commit();
        }

        for (int c = 0; c < NCH; c++) {
            if (c < NCH - 1) cp_wait<1>(); else cp_wait<0>();
            __syncthreads();
            if (c + 2 < NCH) {
                float* db = Ab + ((c + 2) % NSTG) * KC * ASTR;
                const float* sb = hTp + (size_t)(c + 2) * KC * BATCH;
#pragma unroll
                for (int w = 0; w < 2; w++) {
                    int i = tid + w * 256;
                    int k = i >> 4, c16 = i & 15;
                    cp16(db + k * ASTR + c16 * 4, sb + k * BATCH + c16 * 4);
                }
                cp_commit();
            }
            const float* A = Ab + (c % NSTG) * KC * ASTR;
            const int kbase = c * KC;
#pragma unroll
            for (int kk = 0; kk < KC; kk += 8) {
                unsigned a[4], bf[3][2];
                a[0] = __float_as_uint(A[(kk + tig) * ASTR + mb + gid]);
                a[1] = __float_as_uint(A[(kk + tig) * ASTR + mb + gid + 8]);
                a[2] = __float_as_uint(A[(kk + tig + 4) * ASTR + mb + gid]);
                a[3] = __float_as_uint(A[(kk + tig + 4) * ASTR + mb + gid + 8]);
#pragma unroll
                for (int nt = 0; nt < 3; nt++) {
                    int n = nb + nt * 8 + gid;
                    bf[nt][0] = __float_as_uint(Us[(kbase + kk + tig) * CCOLS + n]);
                    bf[nt][1] = __float_as_uint(Us[(kbase + kk + tig + 4) * CCOLS + n]);
                }
#pragma unroll
                for (int nt = 0; nt < 3; nt++) mma_tf32(acc[nt], a, bf[nt]);
            }
        }
        __syncthreads();

        // stage accumulators so each thread sees all 3 gates of its cells
#pragma unroll
        for (int nt = 0; nt < 3; nt++) {
            int n = nb + nt * 8 + 2 * tig;
            HU[(mb + gid) * HUSTR + n]         = acc[nt][0];
            HU[(mb + gid) * HUSTR + n + 1]     = acc[nt][1];
            HU[(mb + gid + 8) * HUSTR + n]     = acc[nt][2];
            HU[(mb + gid + 8) * HUSTR + n + 1] = acc[nt][3];
        }
        __syncthreads();

        // gate epilogue: 4 cells per thread (b = eb, u = u0+eu4..+3)
        const int wb = 1 - rb;
        const int m  = tid >> 2;
        float hn4[4];
        const float xz[4] = {xz4.x, xz4.y, xz4.z, xz4.w};
        const float xr[4] = {xr4.x, xr4.y, xr4.z, xr4.w};
        const float xh[4] = {xh4.x, xh4.y, xh4.z, xh4.w};
        const float hp[4] = {hp4.x, hp4.y, hp4.z, hp4.w};
#pragma unroll
        for (int j = 0; j < 4; j++) {
            int uu = eu4 + j;
            float hz = HU[m * HUSTR + uu]          + sbias[uu];
            float hr = HU[m * HUSTR + UB + uu]     + sbias[UB + uu];
            float hh = HU[m * HUSTR + 2 * UB + uu] + sbias[2 * UB + uu];
            float z    = 1.f / (1.f + __expf(-(xz[j] + hz)));
            float rg   = 1.f / (1.f + __expf(-(xr[j] + hr)));
            float hhat = tanhf(xh[j] + rg * hh);
            float hn   = z * hp[j] + (1.f - z) * hhat;
            hn4[j] = hn;
            g_hT[wb][u0 + uu][eb] = tf32r(hn);
        }
        *(float4*)(g_hF + (size_t)eb * UNITS + u0 + eu4) =
            make_float4(hn4[0], hn4[1], hn4[2], hn4[3]);
        size_t yi = ((size_t)eb * TSEQ + t) * UNITS + u0 + eu4;
        if (is_last) {
            *(float4*)(yout + yi) = make_float4(hn4[0], hn4[1], hn4[2], hn4[3]);
        } else {
            *(float4*)(g_x + yi) =
                make_float4(tf32r(hn4[0]), tf32r(hn4[1]), tf32r(hn4[2]), tf32r(hn4[3]));
        }
        grid_sync();
    }

    // final states
    {
        float4 hv = *(const float4*)(g_hF + (size_t)eb * UNITS + u0 + eu4);
        float* d = out_states + ((size_t)eb * UNITS + u0 + eu4) * LAYERS + layer;
        d[0] = hv.x; d[3] = hv.y; d[6] = hv.z; d[9] = hv.w;
    }
}

// ---------------- host launcher ----------------
#define PERS_SMEM ((UNITS * CCOLS + NSTG * KC * ASTR + 64) * 4)

extern "C" void kernel_launch(void* const* d_in, const int* in_sizes, int n_in,
                              void* d_out, int out_size) {
    (void)in_sizes; (void)n_in; (void)out_size;
    const float* x_in = (const float*)d_in[0];
    const float* h0   = (const float*)d_in[1];
    const float* W    = (const float*)d_in[2];
    const float* U    = (const float*)d_in[3];
    const float* b    = (const float*)d_in[4];
    float* out        = (float*)d_out;
    float* out_states = out + (size_t)MXW * UNITS;

    static float* g_x_ptr = nullptr;
    if (!g_x_ptr) cudaGetSymbolAddress((void**)&g_x_ptr, g_x);

    cudaFuncSetAttribute(gru_layer_kernel,
                         cudaFuncAttributeMaxDynamicSharedMemorySize, PERS_SMEM);

    for (int l = 0; l < LAYERS; l++) {
        const float* A = (l == 0) ? x_in : g_x_ptr;
        gemm_xw_kernel<<<dim3(NC / BN, MXW / BM), 256>>>(
            A, W + (size_t)l * UNITS * NC, b + (size_t)l * 2 * NC);
        gru_layer_kernel<<<dim3(UGRP, 2), 256, PERS_SMEM>>>(
            l, h0, U, b + (size_t)l * 2 * NC + NC, out, out_states, l == LAYERS - 1);
    }
}

// round 6
// speedup vs baseline: 1.0453x; 1.0453x over previous
#include <cuda_runtime.h>
#include <cstdint>
#include <math.h>

#define LAYERS 3
#define UNITS  1024
#define BATCH  128
#define TSEQ   256
#define NC     (3*UNITS)      // 3072
#define MXW    (BATCH*TSEQ)   // 32768

// recurrent geometry: grid = 64 u-groups x 2 batch-halves = 128 CTAs (co-resident)
#define UGRP   64
#define UB     16             // u-indices per CTA -> 48 cols (z|r|hh)
#define CCOLS  48
#define MROWS  64             // batch rows per CTA
#define HUSTR  49

// ---------------- scratch (static device memory) ----------------
__device__ __align__(128) float g_xw[(size_t)MXW * NC];      // [t][b][3U]
__device__ __align__(128) float g_x [(size_t)MXW * UNITS];   // activations (tf32-rounded)
__device__ __align__(128) float g_Wc[(size_t)LAYERS * UNITS * NC]; // tf32-rounded W
__device__ __align__(128) float g_hT[2][UNITS][BATCH];       // tf32 h, transposed
__device__ __align__(128) float g_hF[BATCH * UNITS];         // full-precision h
__device__ int g_flag[2][UGRP];                              // [half][ugroup] = state published

// ---------------- helpers ----------------
__device__ __forceinline__ float tf32r(float v) {
    unsigned r;
    asm("cvt.rna.tf32.f32 %0, %1;" : "=r"(r) : "f"(v));
    return __uint_as_float(r);
}

__device__ __forceinline__ void mma_tf32(float* c, const unsigned* a, const unsigned* b) {
    asm volatile(
        "mma.sync.aligned.m16n8k8.row.col.f32.tf32.tf32.f32 "
        "{%0,%1,%2,%3}, {%4,%5,%6,%7}, {%8,%9}, {%0,%1,%2,%3};"
        : "+f"(c[0]), "+f"(c[1]), "+f"(c[2]), "+f"(c[3])
        : "r"(a[0]), "r"(a[1]), "r"(a[2]), "r"(a[3]), "r"(b[0]), "r"(b[1]));
}

__device__ __forceinline__ void cp16(float* dst, const float* src) {
    unsigned ds = (unsigned)__cvta_generic_to_shared(dst);
    asm volatile("cp.async.cg.shared.global [%0], [%1], 16;" :: "r"(ds), "l"(src));
}
__device__ __forceinline__ void cp_commit() { asm volatile("cp.async.commit_group;"); }
template <int N> __device__ __forceinline__ void cp_wait() {
    asm volatile("cp.async.wait_group %0;" :: "n"(N));
}

__device__ __forceinline__ int ldacq(const int* p) {
    int v;
    asm volatile("ld.acquire.gpu.global.b32 %0, [%1];" : "=r"(v) : "l"(p));
    return v;
}
__device__ __forceinline__ void strel(int* p, int v) {
    asm volatile("st.release.gpu.global.b32 [%0], %1;" :: "l"(p), "r"(v));
}
__device__ __forceinline__ void wait_flag(const int* p, int t) {
    if (ldacq(p) >= t) return;
    while (ldacq(p) < t) { __nanosleep(20); }
}

// ---------------- small kernels ----------------
__global__ void reset_flags_kernel() {
    if (threadIdx.x < 2 * UGRP) ((int*)g_flag)[threadIdx.x] = -1;
}
__global__ void cvt_weights_kernel(const float* __restrict__ W) {
    size_t n = (size_t)LAYERS * UNITS * NC;
    for (size_t i = blockIdx.x * (size_t)blockDim.x + threadIdx.x; i < n;
         i += (size_t)gridDim.x * blockDim.x)
        g_Wc[i] = tf32r(W[i]);
}
__global__ void cvt_input_kernel(const float* __restrict__ X) {
    size_t n = (size_t)MXW * UNITS;
    for (size_t i = blockIdx.x * (size_t)blockDim.x + threadIdx.x; i < n;
         i += (size_t)gridDim.x * blockDim.x)
        g_x[i] = tf32r(X[i]);
}

// ---------------- XW GEMM: g_xw[t][b][:] = (g_x @ Wc[l]) + b0[l] ----------------
// 3-stage cp.async pipeline. A smem [m][k] stride 36, B smem [k][n] stride 136.
#define BM 128
#define BN 128
#define BK 32
#define XA_STR 36
#define XB_STR 136
#define XA_SZ (BM * XA_STR)          // 4608 floats
#define XB_SZ (BK * XB_STR)          // 4352 floats
#define X_STAGE (XA_SZ + XB_SZ)      // 8960 floats
#define XW_SMEM (3 * X_STAGE * 4)    // 107520 bytes

__device__ __forceinline__ void xw_load_stage(float* st, const float* __restrict__ A,
                                              const float* __restrict__ Bw,
                                              int bm0, int bn0, int k0, int tid) {
    float* As2 = st;
    float* Bs2 = st + XA_SZ;
#pragma unroll
    for (int j = 0; j < 4; j++) {
        int i = tid + j * 256;
        int m = i >> 3, c4 = i & 7;
        cp16(As2 + m * XA_STR + c4 * 4, A + (size_t)(bm0 + m) * UNITS + k0 + c4 * 4);
    }
#pragma unroll
    for (int j = 0; j < 4; j++) {
        int i = tid + j * 256;
        int r = i >> 5, c4 = i & 31;
        cp16(Bs2 + r * XB_STR + c4 * 4, Bw + (size_t)(k0 + r) * NC + bn0 + c4 * 4);
    }
    cp_commit();
}

__global__ __launch_bounds__(256) void gemm_xw_kernel(const float* __restrict__ A,
                                                      const float* __restrict__ Bw,
                                                      const float* __restrict__ bias) {
    extern __shared__ float smx[];
    float* C = g_xw;

    int tid = threadIdx.x;
    int lane = tid & 31, wid = tid >> 5;
    int gid = lane >> 2, tig = lane & 3;
    int wm = wid & 3, wn = wid >> 2;
    int mb = wm * 32, nb = wn * 64;
    int bm0 = blockIdx.y * BM, bn0 = blockIdx.x * BN;

    float acc[2][8][4];
#pragma unroll
    for (int i = 0; i < 2; i++)
#pragma unroll
        for (int j = 0; j < 8; j++)
#pragma unroll
            for (int q = 0; q < 4; q++) acc[i][j][q] = 0.f;

    xw_load_stage(smx, A, Bw, bm0, bn0, 0, tid);
    xw_load_stage(smx + X_STAGE, A, Bw, bm0, bn0, BK, tid);

    const int NIT = UNITS / BK;   // 32
    for (int it = 0; it < NIT; it++) {
        if (it < NIT - 1) cp_wait<1>(); else cp_wait<0>();
        __syncthreads();
        if (it + 2 < NIT)
            xw_load_stage(smx + ((it + 2) % 3) * X_STAGE, A, Bw, bm0, bn0, (it + 2) * BK, tid);

        const float* As2 = smx + (it % 3) * X_STAGE;
        const float* Bs2 = As2 + XA_SZ;
#pragma unroll
        for (int kk = 0; kk < BK; kk += 8) {
            unsigned a[2][4], bf[8][2];
#pragma unroll
            for (int mt = 0; mt < 2; mt++) {
                int m = mb + mt * 16 + gid;
                a[mt][0] = __float_as_uint(As2[m * XA_STR + kk + tig]);
                a[mt][1] = __float_as_uint(As2[(m + 8) * XA_STR + kk + tig]);
                a[mt][2] = __float_as_uint(As2[m * XA_STR + kk + tig + 4]);
                a[mt][3] = __float_as_uint(As2[(m + 8) * XA_STR + kk + tig + 4]);
            }
#pragma unroll
            for (int nt = 0; nt < 8; nt++) {
                int n = nb + nt * 8 + gid;
                bf[nt][0] = __float_as_uint(Bs2[(kk + tig) * XB_STR + n]);
                bf[nt][1] = __float_as_uint(Bs2[(kk + tig + 4) * XB_STR + n]);
            }
#pragma unroll
            for (int mt = 0; mt < 2; mt++)
#pragma unroll
                for (int nt = 0; nt < 8; nt++) mma_tf32(acc[mt][nt], a[mt], bf[nt]);
        }
        __syncthreads();
    }
#pragma unroll
    for (int mt = 0; mt < 2; mt++) {
#pragma unroll
        for (int nt = 0; nt < 8; nt++) {
            int m0 = bm0 + mb + mt * 16 + gid;    // row = b*TSEQ + t
            int n  = bn0 + nb + nt * 8 + 2 * tig;
            float bv0 = bias[n], bv1 = bias[n + 1];
            int t0 = m0 & (TSEQ - 1), b0r = m0 >> 8;
            int m1 = m0 + 8;
            int t1 = m1 & (TSEQ - 1), b1r = m1 >> 8;
            size_t r0 = ((size_t)t0 * BATCH + b0r) * NC + n;
            size_t r1 = ((size_t)t1 * BATCH + b1r) * NC + n;
            C[r0]     = acc[mt][nt][0] + bv0;
            C[r0 + 1] = acc[mt][nt][1] + bv1;
            C[r1]     = acc[mt][nt][2] + bv0;
            C[r1 + 1] = acc[mt][nt][3] + bv1;
        }
    }
}

// ---------------- persistent GRU layer kernel (warp-autonomous mainloop) ----------------
// grid (UGRP, 2). 256 threads = 8 warps: wm(2) x wk(4). Warp tile m32 x n48,
// k-quarter 256 rows. A-frags via pipelined LDG from g_hT; U fragment-major in smem.
// smem: Up2 (float2[128][6][32]) | HU[64][49] | sbias[48]
#define GRU_SMEM ((49152 + 64 * HUSTR + 48 + 8) * 4)

__global__ __launch_bounds__(256, 1)
void gru_layer_kernel(int layer, const float* __restrict__ h0,
                      const float* __restrict__ U_raw,
                      const float* __restrict__ bias1,
                      float* __restrict__ yout, float* __restrict__ out_states,
                      int is_last) {
    extern __shared__ float sm[];
    float2* Up2  = (float2*)sm;                 // 24576 float2
    float*  HU   = sm + 49152;                  // [64][49]
    float*  sbias = HU + 64 * HUSTR;            // [48]

    const int tid  = threadIdx.x;
    const int lane = tid & 31, wid = tid >> 5;
    const int gid  = lane >> 2, tig = lane & 3;
    const int wm   = wid & 1, wk = wid >> 1;    // m-half, k-quarter
    const int mb   = wm * 32;
    const int kq   = wk * 32;                   // warp's first global k8 index
    const int GQ   = wk * 16;                   // warp's first producer ugroup
    const int cm0  = mb + gid;                  // m col for mt=0
    const int cm1  = mb + 16 + gid;             // m col for mt=1
    const int u0   = blockIdx.x * UB;
    const int bh   = blockIdx.y;
    const int b0g  = bh * MROWS;

    // --- load U slice in fragment-major layout (once per layer) ---
    // Up2[(k8*6 + nt)*32 + lane] = (U[8k8+tig][col], U[8k8+tig+4][col]), col = nt*8+gid
    const float* Uc = U_raw + (size_t)layer * UNITS * NC;
    for (int i = tid; i < 128 * 6 * 32; i += 256) {
        int l2   = i & 31;
        int nt   = (i >> 5) % 6;
        int k8   = i / (6 * 32);
        int ltig = l2 & 3, lgid = l2 >> 2;
        int col  = nt * 8 + lgid;
        int gate = col >> 4, uu = col & 15;
        size_t cofs = (size_t)gate * UNITS + u0 + uu;
        float v0 = tf32r(Uc[(size_t)(8 * k8 + ltig) * NC + cofs]);
        float v1 = tf32r(Uc[(size_t)(8 * k8 + ltig + 4) * NC + cofs]);
        Up2[i] = make_float2(v0, v1);
    }
    if (tid < CCOLS) {
        int gate = tid >> 4, uu = tid & 15;
        sbias[tid] = bias1[gate * UNITS + u0 + uu];
    }

    // epilogue cell ownership: b = b0g + (tid>>2), u = u0 + (tid&3)*4 + j
    const int eb  = b0g + (tid >> 2);
    const int eu4 = (tid & 3) * 4;

    // init h: full precision -> g_hF, tf32 transposed -> g_hT[0]; publish state 0
    {
        float4 hv;
        const float* src = h0 + ((size_t)eb * UNITS + u0 + eu4) * LAYERS + layer;
        hv.x = src[0]; hv.y = src[3]; hv.z = src[6]; hv.w = src[9];
        *(float4*)(g_hF + (size_t)eb * UNITS + u0 + eu4) = hv;
        g_hT[0][u0 + eu4 + 0][eb] = tf32r(hv.x);
        g_hT[0][u0 + eu4 + 1][eb] = tf32r(hv.y);
        g_hT[0][u0 + eu4 + 2][eb] = tf32r(hv.z);
        g_hT[0][u0 + eu4 + 3][eb] = tf32r(hv.w);
    }
    __threadfence();
    __syncthreads();
    if (tid == 0) strel(&g_flag[bh][blockIdx.x], 0);

#define PREFETCH(slot, step) do {                                              \
        const float* rp = hTp + (size_t)((kq + (step)) * 8 + tig) * BATCH;     \
        const float* rp4 = rp + 4 * BATCH;                                     \
        ar[slot][0][0] = __float_as_uint(rp[cm0]);                             \
        ar[slot][0][1] = __float_as_uint(rp[cm0 + 8]);                         \
        ar[slot][1][0] = __float_as_uint(rp[cm1]);                             \
        ar[slot][1][1] = __float_as_uint(rp[cm1 + 8]);                         \
        ar[slot][0][2] = __float_as_uint(rp4[cm0]);                            \
        ar[slot][0][3] = __float_as_uint(rp4[cm0 + 8]);                        \
        ar[slot][1][2] = __float_as_uint(rp4[cm1]);                            \
        ar[slot][1][3] = __float_as_uint(rp4[cm1 + 8]);                        \
    } while (0)

    for (int t = 0; t < TSEQ; t++) {
        const int rb = t & 1;
        const float* hTp = &g_hT[rb][0][b0g];

        // prefetch epilogue operands (own data)
        const float* xwrow = g_xw + ((size_t)t * BATCH + eb) * NC + u0 + eu4;
        float4 xz4 = *(const float4*)(xwrow);
        float4 xr4 = *(const float4*)(xwrow + UNITS);
        float4 xh4 = *(const float4*)(xwrow + 2 * UNITS);
        float4 hp4 = *(const float4*)(g_hF + (size_t)eb * UNITS + u0 + eu4);

        float acc[2][6][4];
#pragma unroll
        for (int i = 0; i < 2; i++)
#pragma unroll
            for (int j = 0; j < 6; j++)
#pragma unroll
                for (int q = 0; q < 4; q++) acc[i][j][q] = 0.f;

        unsigned ar[4][2][4];
        // prologue: prefetch steps 0..3 (groups GQ, GQ+1)
        wait_flag(&g_flag[bh][GQ], t);
        PREFETCH(0, 0);
        PREFETCH(1, 1);
        wait_flag(&g_flag[bh][GQ + 1], t);
        PREFETCH(2, 2);
        PREFETCH(3, 3);

        for (int s = 0; s < 32; s += 4) {
#pragma unroll
            for (int j = 0; j < 4; j++) {
                const int u = s + j;
                const int gk8 = kq + u;
                float2 bq[6];
#pragma unroll
                for (int nt = 0; nt < 6; nt++) bq[nt] = Up2[(gk8 * 6 + nt) * 32 + lane];
                unsigned bfr[6][2];
#pragma unroll
                for (int nt = 0; nt < 6; nt++) {
                    bfr[nt][0] = __float_as_uint(bq[nt].x);
                    bfr[nt][1] = __float_as_uint(bq[nt].y);
                }
#pragma unroll
                for (int mt = 0; mt < 2; mt++)
#pragma unroll
                    for (int nt = 0; nt < 6; nt++) mma_tf32(acc[mt][nt], ar[j][mt], bfr[nt]);
                if (u < 28) {
                    if ((j & 1) == 0)   // (u&1)==0 since s%4==0: new producer group
                        wait_flag(&g_flag[bh][(kq + u + 4) >> 1], t);
                    PREFETCH(j, u + 4);
                }
            }
        }
        __syncthreads();

        // k-split merge: 4 sequential passes over HU
#pragma unroll
        for (int pass = 0; pass < 4; pass++) {
            if (wk == pass) {
#pragma unroll
                for (int mt = 0; mt < 2; mt++)
#pragma unroll
                    for (int nt = 0; nt < 6; nt++) {
                        int m = mb + mt * 16 + gid;
                        int n = nt * 8 + 2 * tig;
                        if (pass == 0) {
                            HU[m * HUSTR + n]           = acc[mt][nt][0];
                            HU[m * HUSTR + n + 1]       = acc[mt][nt][1];
                            HU[(m + 8) * HUSTR + n]     = acc[mt][nt][2];
                            HU[(m + 8) * HUSTR + n + 1] = acc[mt][nt][3];
                        } else {
                            HU[m * HUSTR + n]           += acc[mt][nt][0];
                            HU[m * HUSTR + n + 1]       += acc[mt][nt][1];
                            HU[(m + 8) * HUSTR + n]     += acc[mt][nt][2];
                            HU[(m + 8) * HUSTR + n + 1] += acc[mt][nt][3];
                        }
                    }
            }
            __syncthreads();
        }

        // gate epilogue: 4 cells per thread
        const int wb = 1 - rb;
        const int m  = tid >> 2;
        float hn4[4];
        const float xz[4] = {xz4.x, xz4.y, xz4.z, xz4.w};
        const float xr[4] = {xr4.x, xr4.y, xr4.z, xr4.w};
        const float xh[4] = {xh4.x, xh4.y, xh4.z, xh4.w};
        const float hp[4] = {hp4.x, hp4.y, hp4.z, hp4.w};
#pragma unroll
        for (int j = 0; j < 4; j++) {
            int uu = eu4 + j;
            float hz = HU[m * HUSTR + uu]          + sbias[uu];
            float hr = HU[m * HUSTR + UB + uu]     + sbias[UB + uu];
            float hh = HU[m * HUSTR + 2 * UB + uu] + sbias[2 * UB + uu];
            float z    = 1.f / (1.f + __expf(-(xz[j] + hz)));
            float rg   = 1.f / (1.f + __expf(-(xr[j] + hr)));
            float hhat = tanhf(xh[j] + rg * hh);
            float hn   = z * hp[j] + (1.f - z) * hhat;
            hn4[j] = hn;
            g_hT[wb][u0 + uu][eb] = tf32r(hn);
        }
        *(float4*)(g_hF + (size_t)eb * UNITS + u0 + eu4) =
            make_float4(hn4[0], hn4[1], hn4[2], hn4[3]);
        size_t yi = ((size_t)eb * TSEQ + t) * UNITS + u0 + eu4;
        if (is_last) {
            *(float4*)(yout + yi) = make_float4(hn4[0], hn4[1], hn4[2], hn4[3]);
        } else {
            *(float4*)(g_x + yi) =
                make_float4(tf32r(hn4[0]), tf32r(hn4[1]), tf32r(hn4[2]), tf32r(hn4[3]));
        }

        // publish state t+1
        __threadfence();
        __syncthreads();
        if (tid == 0) strel(&g_flag[bh][blockIdx.x], t + 1);
    }
#undef PREFETCH

    // final states
    {
        float4 hv = *(const float4*)(g_hF + (size_t)eb * UNITS + u0 + eu4);
        float* d = out_states + ((size_t)eb * UNITS + u0 + eu4) * LAYERS + layer;
        d[0] = hv.x; d[3] = hv.y; d[6] = hv.z; d[9] = hv.w;
    }
}

// ---------------- host launcher ----------------
extern "C" void kernel_launch(void* const* d_in, const int* in_sizes, int n_in,
                              void* d_out, int out_size) {
    (void)in_sizes; (void)n_in; (void)out_size;
    const float* x_in = (const float*)d_in[0];
    const float* h0   = (const float*)d_in[1];
    const float* W    = (const float*)d_in[2];
    const float* U    = (const float*)d_in[3];
    const float* b    = (const float*)d_in[4];
    float* out        = (float*)d_out;
    float* out_states = out + (size_t)MXW * UNITS;

    static float* g_x_ptr = nullptr;
    static float* g_Wc_ptr = nullptr;
    if (!g_x_ptr)  cudaGetSymbolAddress((void**)&g_x_ptr, g_x);
    if (!g_Wc_ptr) cudaGetSymbolAddress((void**)&g_Wc_ptr, g_Wc);

    cudaFuncSetAttribute(gru_layer_kernel,
                         cudaFuncAttributeMaxDynamicSharedMemorySize, GRU_SMEM);
    cudaFuncSetAttribute(gemm_xw_kernel,
                         cudaFuncAttributeMaxDynamicSharedMemorySize, XW_SMEM);

    cvt_weights_kernel<<<4096, 256>>>(W);
    cvt_input_kernel<<<8192, 256>>>(x_in);

    for (int l = 0; l < LAYERS; l++) {
        gemm_xw_kernel<<<dim3(NC / BN, MXW / BM), 256, XW_SMEM>>>(
            g_x_ptr, g_Wc_ptr + (size_t)l * UNITS * NC, b + (size_t)l * 2 * NC);
        reset_flags_kernel<<<1, 128>>>();
        gru_layer_kernel<<<dim3(UGRP, 2), 256, GRU_SMEM>>>(
            l, h0, U, b + (size_t)l * 2 * NC + NC, out, out_states, l == LAYERS - 1);
    }
}